// round 4
// baseline (speedup 1.0000x reference)
#include <cuda_runtime.h>
#include <cuda_bf16.h>

#define NB   128
#define NN   200000
#define BN   25600000          // NB*NN
#define WPR  6250              // mask words per row (NN/32)
#define RSEG 4
#define SEGW 1563              // words per segment (last seg: 1561)
#define T1   512
#define CAP  4096
#define TILE0 4096
#define POS_T 0.35f
#define NEG_T 0.15f

// ---------------- scratch (device globals; no allocation in kernel_launch) ----
__device__ unsigned int       g_posmask[NB * WPR];
__device__ unsigned long long g_seglists[NB * RSEG * 2 * 64];
__device__ unsigned int       g_segcnt[NB * RSEG * 2];
__device__ unsigned int       g_selidx[NB * 64];
__device__ int                g_selcnt[NB];
__device__ float              g_wscore[NB];
__device__ float              g_wbbox[NB];

// key = ordered(float) << 32 | (0xFFFFFFFF - idx)  -> descending key order ==
// descending value, ties broken by ascending index (stable argsort semantics)
__device__ __forceinline__ unsigned long long mkkey(float v, unsigned idx) {
    unsigned u = __float_as_uint(v);
    u ^= (unsigned)((int)u >> 31) | 0x80000000u;
    return ((unsigned long long)u << 32) | (unsigned long long)(0xFFFFFFFFu - idx);
}

// in-place ascending bitonic sort of a[0..n), n = power of two, block-wide
__device__ void bsort(unsigned long long* a, int n) {
    for (int k = 2; k <= n; k <<= 1) {
        for (int j = k >> 1; j > 0; j >>= 1) {
            __syncthreads();
            for (int i = threadIdx.x; i < n; i += blockDim.x) {
                int l = i ^ j;
                if (l > i) {
                    unsigned long long x = a[i], y = a[l];
                    if ((x > y) == ((i & k) == 0)) { a[i] = y; a[l] = x; }
                }
            }
        }
    }
    __syncthreads();
}

// ---------------- K1: stream inputs once; masks, counts, per-segment top-64 ---
__global__ __launch_bounds__(T1) void k_select(const float* __restrict__ ov,
                                               const float* __restrict__ npz,
                                               const float* __restrict__ nnz) {
    extern __shared__ unsigned long long sh[];
    unsigned long long* listP = sh;
    unsigned long long* listN = sh + CAP;
    __shared__ int cntP, cntN;
    __shared__ int wcP[16], wcN[16];

    const int blk = blockIdx.x;
    const int row = blk >> 2, seg = blk & 3;
    const int w0 = seg * SEGW;
    const int w1 = min(WPR, w0 + SEGW);
    const int L = (w1 - w0) << 5;            // elements in this segment (mult of 32)
    const int ebase = w0 << 5;               // element offset within row
    const int base = row * NN + ebase;
    const int tid = threadIdx.x, lane = tid & 31, wid = tid >> 5;

    int accP = 0, accN = 0;                  // lane0 per-warp mask counts
    unsigned long long cutP = 0ull, cutN = 0ull;
    const int iters = (L + T1 - 1) / T1;

    for (int it = 0; it < iters; ++it) {
        const int el = it * T1 + tid;
        const bool valid = el < L;
        float o = 1e9f, vp = 0.f, vn = 0.f;
        if (valid) {
            o  = __ldg(ov  + base + el);
            vp = __ldg(npz + base + el);
            vn = __ldg(nnz + base + el);
        }
        const bool p  = valid && (o >= POS_T);
        const bool ng = valid && (o < NEG_T);
        unsigned pm = __ballot_sync(0xffffffffu, p);
        unsigned nm = __ballot_sync(0xffffffffu, ng);
        if (lane == 0) {
            accP += __popc(pm); accN += __popc(nm);
            if (valid) g_posmask[row * WPR + w0 + it * 16 + wid] = pm;
        }
        if (it < 8) {                        // calibration tile (always fully valid)
            listP[el] = p  ? mkkey(vp, ebase + el) : 0ull;
            listN[el] = ng ? mkkey(vn, ebase + el) : 0ull;
        } else {
            if (p) {
                unsigned long long k = mkkey(vp, ebase + el);
                if (k > cutP) { int q = atomicAdd(&cntP, 1); if (q < CAP) listP[q] = k; }
            }
            if (ng) {
                unsigned long long k = mkkey(vn, ebase + el);
                if (k > cutN) { int q = atomicAdd(&cntN, 1); if (q < CAP) listN[q] = k; }
            }
        }
        if (it == 7) {                       // calibrate: exact top-64 of tile0
            bsort(listP, TILE0);
            bsort(listN, TILE0);
            cutP = listP[TILE0 - 64];        // conservative cutoff (<= segment 64th)
            cutN = listN[TILE0 - 64];
            if (tid < 64) {                  // keep tile0 top-64 at the front
                listP[tid] = listP[TILE0 - 1 - tid];
                listN[tid] = listN[TILE0 - 1 - tid];
            }
            if (tid == 0) { cntP = 64; cntN = 64; }
            __syncthreads();
        }
    }
    if (lane == 0) { wcP[wid] = accP; wcN[wid] = accN; }
    __syncthreads();

    int cp = min(cntP, CAP), cn = min(cntN, CAP);
    int n2p = 64; while (n2p < cp) n2p <<= 1;
    int n2n = 64; while (n2n < cn) n2n <<= 1;
    for (int i = cp + tid; i < n2p; i += T1) listP[i] = 0ull;
    for (int i = cn + tid; i < n2n; i += T1) listN[i] = 0ull;
    bsort(listP, n2p);
    bsort(listN, n2n);
    if (tid < 64) {
        g_seglists[((blk * 2 + 0) << 6) + tid] = listP[n2p - 1 - tid];
        g_seglists[((blk * 2 + 1) << 6) + tid] = listN[n2n - 1 - tid];
    }
    if (tid == 0) {
        int sp = 0, sn = 0;
        for (int i = 0; i < 16; i++) { sp += wcP[i]; sn += wcN[i]; }
        g_segcnt[blk * 2 + 0] = sp;
        g_segcnt[blk * 2 + 1] = sn;
    }
}

// ---------------- K2: merge per-row, pick selected set + weights --------------
__global__ void k_merge() {
    __shared__ unsigned long long arr[256];
    const int row = blockIdx.x, tid = threadIdx.x;   // 256 threads
    int pc = 0, nc = 0;
#pragma unroll
    for (int s = 0; s < 4; s++) {
        pc += g_segcnt[(row * 4 + s) * 2 + 0];
        nc += g_segcnt[(row * 4 + s) * 2 + 1];
    }
    const int pos_num = min(32, pc);
    const int neg_num = min(64 - pos_num, nc);

    arr[tid] = g_seglists[(((row * 4 + (tid >> 6)) * 2 + 0) << 6) + (tid & 63)];
    bsort(arr, 256);
    if (tid < pos_num)
        g_selidx[(row << 6) + tid] = 0xFFFFFFFFu - (unsigned)(arr[255 - tid] & 0xFFFFFFFFull);
    __syncthreads();

    arr[tid] = g_seglists[(((row * 4 + (tid >> 6)) * 2 + 1) << 6) + (tid & 63)];
    bsort(arr, 256);
    if (tid < neg_num)
        g_selidx[(row << 6) + pos_num + tid] =
            0xFFFFFFFFu - (unsigned)(arr[255 - tid] & 0xFFFFFFFFull);

    if (tid == 0) {
        int sc = pos_num + neg_num;
        g_selcnt[row] = sc;
        g_wscore[row] = 1.0f / ((float)(sc > 0 ? sc : 1) * (float)NB);
        g_wbbox[row]  = 1.0f / ((float)(pc > 0 ? pc : 1) * (float)NB);
    }
}

// ---------------- K3: write all outputs from the bitmask ----------------------
__global__ __launch_bounds__(256) void k_out(float* __restrict__ out) {
    const int w = blockIdx.x * 256 + threadIdx.x;     // word index, < NB*WPR
    const unsigned m = g_posmask[w];
    const int row = w / WPR;
    const float wb = g_wbbox[row];
    float4* lab = reinterpret_cast<float4*>(out) + (w << 3);
    float4* sco = reinterpret_cast<float4*>(out + BN) + (w << 3);
    float4* bbx = reinterpret_cast<float4*>(out + 2 * BN) + (w << 3);
    const float4 z = make_float4(0.f, 0.f, 0.f, 0.f);
#pragma unroll
    for (int q = 0; q < 8; q++) {
        float4 lv;
        lv.x = (m >> (4 * q + 0)) & 1 ? 1.f : 0.f;
        lv.y = (m >> (4 * q + 1)) & 1 ? 1.f : 0.f;
        lv.z = (m >> (4 * q + 2)) & 1 ? 1.f : 0.f;
        lv.w = (m >> (4 * q + 3)) & 1 ? 1.f : 0.f;
        float4 bv = make_float4(lv.x * wb, lv.y * wb, lv.z * wb, lv.w * wb);
        lab[q] = lv;
        sco[q] = z;
        bbx[q] = bv;
    }
}

// ---------------- K4: scatter selected score weights --------------------------
__global__ void k_scatter(float* __restrict__ out) {
    const int row = blockIdx.x, t = threadIdx.x;      // 64 threads
    if (t < g_selcnt[row])
        out[BN + row * NN + (int)g_selidx[(row << 6) + t]] = g_wscore[row];
}

extern "C" void kernel_launch(void* const* d_in, const int* in_sizes, int n_in,
                              void* d_out, int out_size) {
    const float* ov  = (const float*)d_in[0];   // overlaps
    const float* npz = (const float*)d_in[1];   // noise_pos
    const float* nnz = (const float*)d_in[2];   // noise_neg
    float* out = (float*)d_out;                 // [labels | score_weight | bbox_weights]

    cudaFuncSetAttribute(k_select, cudaFuncAttributeMaxDynamicSharedMemorySize,
                         2 * CAP * (int)sizeof(unsigned long long));

    k_select<<<NB * RSEG, T1, 2 * CAP * sizeof(unsigned long long)>>>(ov, npz, nnz);
    k_merge<<<NB, 256>>>();
    k_out<<<(NB * WPR) / 256, 256>>>(out);
    k_scatter<<<NB, 64>>>(out);
}